// round 1
// baseline (speedup 1.0000x reference)
#include <cuda_runtime.h>

#define N_NODES 50000
#define N_EDGES 1600000
#define F_IN    256
#define D       64
#define L       4
#define EPSV    1e-5f
#define ND      (N_NODES * D)

// ---------------- scratch (device globals; no allocation allowed) ----------------
__device__ float  g_W0p[F_IN * D];      // BN-folded W0
__device__ float  g_c0[D];              // BN-folded constant row
__device__ float  g_xw[ND];             // per-layer xw = x @ W
__device__ float  g_sarr[N_NODES];      // s = xw @ a_src
__device__ float  g_tarr[N_NODES];      // t = xw @ a_dst
__device__ float  g_outraw[ND];         // GAT output pre-GraphNorm
__device__ float  g_xs[L * ND];         // per-layer activations (layer input chain + output staging)
__device__ int    g_deg[N_NODES];
__device__ int    g_offs[N_NODES + 1];
__device__ int    g_pos[N_NODES];
__device__ int    g_ssrc[N_EDGES];      // CSR-by-dst: src indices
__device__ double g_sum[D];
__device__ double g_sumsq[D];
__device__ float  g_A[D];
__device__ float  g_B[D];

// ---------------- BN fold ----------------
__global__ void k_prep_w0(const float* __restrict__ W0, const float* __restrict__ bnw,
                          const float* __restrict__ bnv) {
    int i = blockIdx.x * blockDim.x + threadIdx.x;
    if (i < F_IN * D) {
        int f = i / D;
        float g = bnw[f] * rsqrtf(bnv[f] + EPSV);
        g_W0p[i] = g * W0[i];
    }
}

__global__ void k_prep_c0(const float* __restrict__ W0, const float* __restrict__ bnw,
                          const float* __restrict__ bnb, const float* __restrict__ bnm,
                          const float* __restrict__ bnv) {
    int d = threadIdx.x;
    float acc = 0.f;
    for (int f = 0; f < F_IN; ++f) {
        float g = bnw[f] * rsqrtf(bnv[f] + EPSV);
        acc += (bnb[f] - bnm[f] * g) * W0[f * D + d];
    }
    g_c0[d] = acc;
}

// ---------------- CSR build (by dst) ----------------
__global__ void k_zero_deg() {
    int i = blockIdx.x * blockDim.x + threadIdx.x;
    if (i < N_NODES) g_deg[i] = 0;
}

__global__ void k_count(const int* __restrict__ ei) {
    int e = blockIdx.x * blockDim.x + threadIdx.x;
    if (e < N_EDGES) atomicAdd(&g_deg[ei[N_EDGES + e]], 1);
}

__global__ void k_scan() {
    const int CH = (N_NODES + 1023) / 1024;  // 49
    __shared__ int sm[1024];
    int tid = threadIdx.x;
    int base = tid * CH;
    int s = 0;
    for (int j = 0; j < CH; ++j) {
        int idx = base + j;
        if (idx < N_NODES) s += g_deg[idx];
    }
    sm[tid] = s;
    __syncthreads();
    for (int o = 1; o < 1024; o <<= 1) {
        int v = (tid >= o) ? sm[tid - o] : 0;
        __syncthreads();
        sm[tid] += v;
        __syncthreads();
    }
    int run = sm[tid] - s;  // exclusive prefix
    for (int j = 0; j < CH; ++j) {
        int idx = base + j;
        if (idx < N_NODES) {
            g_offs[idx] = run;
            g_pos[idx] = run;
            run += g_deg[idx];
        }
    }
    if (tid == 1023) g_offs[N_NODES] = run;
}

__global__ void k_scatter(const int* __restrict__ ei) {
    int e = blockIdx.x * blockDim.x + threadIdx.x;
    if (e < N_EDGES) {
        int d = ei[N_EDGES + e];
        int slot = atomicAdd(&g_pos[d], 1);
        g_ssrc[slot] = ei[e];
    }
}

// ---------------- GEMM: xw = X @ W (+c0), s = xw@a_src, t = xw@a_dst ----------------
// block = 256 threads = 8 warps; each warp computes 8 rows x 64 cols.
__global__ void __launch_bounds__(256) k_gemm(
    const float* __restrict__ Xin, const float* __restrict__ Win, int K,
    const float* __restrict__ asrc, const float* __restrict__ adst,
    int add_c0, int layer)
{
    __shared__ float Wsm[64 * 64];  // 16 KB chunk
    const float* X = Xin ? Xin : (g_xs + (size_t)(layer - 1) * ND);
    const float* W = Win ? Win : g_W0p;

    int warp = threadIdx.x >> 5, lane = threadIdx.x & 31;
    int row0 = blockIdx.x * 64 + warp * 8;
    float2 acc[8];
#pragma unroll
    for (int r = 0; r < 8; ++r) { acc[r].x = 0.f; acc[r].y = 0.f; }

    for (int kc = 0; kc < K; kc += 64) {
        for (int i = threadIdx.x; i < 64 * 64; i += 256) Wsm[i] = W[kc * 64 + i];
        __syncthreads();
#pragma unroll
        for (int sc = 0; sc < 2; ++sc) {
            float xv[8];
#pragma unroll
            for (int r = 0; r < 8; ++r) {
                int row = row0 + r;
                if (row >= N_NODES) row = N_NODES - 1;
                xv[r] = X[(size_t)row * K + kc + sc * 32 + lane];
            }
#pragma unroll
            for (int j = 0; j < 32; ++j) {
                float2 w2 = *(const float2*)&Wsm[(sc * 32 + j) * 64 + 2 * lane];
#pragma unroll
                for (int r = 0; r < 8; ++r) {
                    float xb = __shfl_sync(0xffffffffu, xv[r], j);
                    acc[r].x += xb * w2.x;
                    acc[r].y += xb * w2.y;
                }
            }
        }
        __syncthreads();
    }

    if (add_c0) {
        float2 cc = *(const float2*)&g_c0[2 * lane];
#pragma unroll
        for (int r = 0; r < 8; ++r) { acc[r].x += cc.x; acc[r].y += cc.y; }
    }

    float2 as2 = *(const float2*)&asrc[2 * lane];
    float2 ad2 = *(const float2*)&adst[2 * lane];
    float2* xw2 = (float2*)g_xw;
#pragma unroll
    for (int r = 0; r < 8; ++r) {
        int row = row0 + r;
        float sp = acc[r].x * as2.x + acc[r].y * as2.y;
        float tp = acc[r].x * ad2.x + acc[r].y * ad2.y;
#pragma unroll
        for (int o = 16; o; o >>= 1) {
            sp += __shfl_xor_sync(0xffffffffu, sp, o);
            tp += __shfl_xor_sync(0xffffffffu, tp, o);
        }
        if (row < N_NODES) {
            xw2[row * 32 + lane] = acc[r];
            if (lane == 0) { g_sarr[row] = sp; g_tarr[row] = tp; }
        }
    }
}

// ---------------- edge aggregation: one warp per dst node ----------------
__global__ void __launch_bounds__(256) k_agg(const float* __restrict__ bias_l) {
    int warp = threadIdx.x >> 5, lane = threadIdx.x & 31;
    int row = blockIdx.x * 8 + warp;
    if (row >= N_NODES) return;

    int beg = g_offs[row], end = g_offs[row + 1];
    float td = g_tarr[row];

    // pass 1: max logit
    float m = -1e30f;
    for (int k = beg + lane; k < end; k += 32) {
        float v = g_sarr[g_ssrc[k]] + td;
        v = v > 0.f ? v : 0.2f * v;
        m = fmaxf(m, v);
    }
#pragma unroll
    for (int o = 16; o; o >>= 1) m = fmaxf(m, __shfl_xor_sync(0xffffffffu, m, o));

    // pass 2: unnormalized weighted sum (recompute logit — cheap, avoids scratch+fence)
    float den = 0.f, ax = 0.f, ay = 0.f;
    const float2* xw2 = (const float2*)g_xw;
#pragma unroll 4
    for (int k = beg; k < end; ++k) {
        int si = g_ssrc[k];                    // broadcast load
        float v = g_sarr[si] + td;             // broadcast load
        v = v > 0.f ? v : 0.2f * v;
        float e = __expf(v - m);
        den += e;
        float2 w = xw2[si * 32 + lane];        // 256B coalesced gather (L2-resident)
        ax += e * w.x;
        ay += e * w.y;
    }
    float inv = (end > beg) ? 1.f / den : 0.f;
    float2 b2 = *(const float2*)&bias_l[2 * lane];
    float2 o2;
    o2.x = ax * inv + b2.x;
    o2.y = ay * inv + b2.y;
    ((float2*)g_outraw)[row * 32 + lane] = o2;
}

// ---------------- GraphNorm ----------------
__global__ void k_zero_stats() {
    int i = threadIdx.x;
    if (i < D) { g_sum[i] = 0.0; g_sumsq[i] = 0.0; }
}

__global__ void __launch_bounds__(256) k_reduce() {
    __shared__ float sh[256], sh2[256];
    int tid = threadIdx.x;
    int f = tid & 63, rep = tid >> 6;
    float s = 0.f, s2 = 0.f;
    for (int r = blockIdx.x * 4 + rep; r < N_NODES; r += gridDim.x * 4) {
        float v = g_outraw[r * 64 + f];
        s += v;
        s2 += v * v;
    }
    sh[tid] = s; sh2[tid] = s2;
    __syncthreads();
    if (rep == 0) {
        s  = sh[f]  + sh[64 + f]  + sh[128 + f]  + sh[192 + f];
        s2 = sh2[f] + sh2[64 + f] + sh2[128 + f] + sh2[192 + f];
        atomicAdd(&g_sum[f],   (double)s);
        atomicAdd(&g_sumsq[f], (double)s2);
    }
}

__global__ void k_finalize(const float* __restrict__ gnw, const float* __restrict__ gnb,
                           const float* __restrict__ gns) {
    int f = threadIdx.x;
    float mean = (float)(g_sum[f]   / (double)N_NODES);
    float ex2  = (float)(g_sumsq[f] / (double)N_NODES);
    float ms = gns[f];
    // E[(x - ms*mean)^2] = E[x^2] - 2*ms*mean*E[x] + ms^2*mean^2
    float var = ex2 - 2.f * ms * mean * mean + ms * ms * mean * mean;
    float a = gnw[f] * rsqrtf(var + EPSV);
    g_A[f] = a;
    g_B[f] = gnb[f] - a * ms * mean;
}

__global__ void __launch_bounds__(256) k_apply(int l) {
    int idx = blockIdx.x * blockDim.x + threadIdx.x;  // over N*32 float2
    if (idx >= N_NODES * 32) return;
    int f2 = idx & 31;
    float2 v = ((const float2*)g_outraw)[idx];
    float2 a = *(const float2*)&g_A[2 * f2];
    float2 b = *(const float2*)&g_B[2 * f2];
    float yx = a.x * v.x + b.x; yx = yx > 0.f ? yx : 0.01f * yx;
    float yy = a.y * v.y + b.y; yy = yy > 0.f ? yy : 0.01f * yy;
    ((float2*)(g_xs + (size_t)l * ND))[idx] = make_float2(yx, yy);
}

// ---------------- final output assembly: x, h, xs ----------------
__global__ void __launch_bounds__(256) k_epilogue(float* __restrict__ out) {
    int idx = blockIdx.x * blockDim.x + threadIdx.x;  // over ND
    if (idx >= ND) return;
    float v0 = g_xs[idx];
    float v1 = g_xs[ND + idx];
    float v2 = g_xs[2 * ND + idx];
    float v3 = g_xs[3 * ND + idx];
    out[idx] = v3;                                  // x (after layer 3)
    out[ND + idx] = 0.5f * (((v0 + v1) + v2) + v3); // h = 0.5 * sum
    ((float4*)(out + 2 * (size_t)ND))[idx] = make_float4(v0, v1, v2, v3);  // xs[idx][0..3]
}

// ---------------- launch ----------------
extern "C" void kernel_launch(void* const* d_in, const int* in_sizes, int n_in,
                              void* d_out, int out_size) {
    const float* x    = (const float*)d_in[0];
    const int*   ei   = (const int*)  d_in[1];
    const float* bnw  = (const float*)d_in[2];
    const float* bnb  = (const float*)d_in[3];
    const float* bnm  = (const float*)d_in[4];
    const float* bnv  = (const float*)d_in[5];
    const float* W0   = (const float*)d_in[6];
    const float* Ws   = (const float*)d_in[7];
    const float* asrc = (const float*)d_in[8];
    const float* adst = (const float*)d_in[9];
    const float* bias = (const float*)d_in[10];
    const float* gnw  = (const float*)d_in[11];
    const float* gnb  = (const float*)d_in[12];
    const float* gns  = (const float*)d_in[13];
    float* out = (float*)d_out;

    k_prep_w0<<<(F_IN * D + 255) / 256, 256>>>(W0, bnw, bnv);
    k_prep_c0<<<1, 64>>>(W0, bnw, bnb, bnm, bnv);

    k_zero_deg<<<(N_NODES + 255) / 256, 256>>>();
    k_count<<<(N_EDGES + 255) / 256, 256>>>(ei);
    k_scan<<<1, 1024>>>();
    k_scatter<<<(N_EDGES + 255) / 256, 256>>>(ei);

    for (int l = 0; l < L; ++l) {
        const float* W = (l == 0) ? nullptr : (Ws + (size_t)(l - 1) * D * D);
        const float* X = (l == 0) ? x : nullptr;
        int K = (l == 0) ? F_IN : D;
        k_gemm<<<(N_NODES + 63) / 64, 256>>>(X, W, K, asrc + l * D, adst + l * D,
                                             (l == 0) ? 1 : 0, l);
        k_agg<<<(N_NODES + 7) / 8, 256>>>(bias + l * D);
        k_zero_stats<<<1, 64>>>();
        k_reduce<<<148, 256>>>();
        k_finalize<<<1, 64>>>(gnw + l * D, gnb + l * D, gns + l * D);
        k_apply<<<(N_NODES * 32 + 255) / 256, 256>>>(l);
    }
    k_epilogue<<<(ND + 255) / 256, 256>>>(out);
}